// round 1
// baseline (speedup 1.0000x reference)
#include <cuda_runtime.h>

// Problem constants
#define BB 8
#define NN 2048
#define DD 256
#define LL 2
#define MROWS (BB * NN)   // 16384

// Scratch (static __device__ arrays — no allocation allowed)
__device__ float g_x[BB * NN * DD];     // current layer input (layer >= 1)
__device__ float g_xWr[BB * NN * DD];   // x @ Wr^T + br
__device__ float g_xW0[BB * NN * DD];   // x @ W0^T + b0
__device__ float g_denom[BB * NN];      // row-sum(adj) + 1

// ---------------------------------------------------------------------------
// denom[b,n] = sum_k adj[b,n,k] + 1     (one warp per row, float4 loads)
// ---------------------------------------------------------------------------
__global__ void denom_kernel(const float* __restrict__ adj) {
    int row  = blockIdx.x * 8 + (threadIdx.x >> 5);   // 8 warps/block
    int lane = threadIdx.x & 31;
    const float4* p = (const float4*)(adj + (size_t)row * NN);
    float s = 0.f;
#pragma unroll 4
    for (int i = lane; i < NN / 4; i += 32) {
        float4 v = p[i];
        s += v.x + v.y + v.z + v.w;
    }
#pragma unroll
    for (int o = 16; o; o >>= 1) s += __shfl_xor_sync(0xffffffffu, s, o);
    if (lane == 0) g_denom[row] = s + 1.0f;
}

// ---------------------------------------------------------------------------
// NT GEMM:  C[n,m] = sum_d X[n,d] * W[m,d] + bias[m]
//   X: [MROWS, DD] row-major (batch flattened), W: [DD, DD] row-major, K = DD
//   64x64 tile, 256 threads, 4x4 microtile, K-tile 16
//   src_is_gx: 0 -> X = nodes (param), 1 -> X = g_x
//   dst_sel:   0 -> g_xWr, 1 -> g_xW0
// ---------------------------------------------------------------------------
__global__ void gemm_nt_kernel(const float* __restrict__ nodes,
                               const float* __restrict__ W,
                               const float* __restrict__ bias,
                               int src_is_gx, int dst_sel) {
    __shared__ float As[64][16];      // [row][k]  (direct copy)
    __shared__ float Bs[16][68];      // [k][col]  (transposed store, pad 4)

    const float* X = src_is_gx ? g_x : nodes;
    float* C = dst_sel ? g_xW0 : g_xWr;

    int tid = threadIdx.x;
    int tx = tid & 15;        // output col group
    int ty = tid >> 4;        // output row group
    int row0 = blockIdx.y * 64;
    int col0 = blockIdx.x * 64;

    int lr = tid >> 2;        // 0..63 : tile row (A) / tile col (W)
    int lk = (tid & 3) * 4;   // k offset

    float acc[4][4] = {};

    for (int k0 = 0; k0 < DD; k0 += 16) {
        float4 a = *(const float4*)(X + (size_t)(row0 + lr) * DD + k0 + lk);
        float4 w = *(const float4*)(W + (size_t)(col0 + lr) * DD + k0 + lk);
        *(float4*)&As[lr][lk] = a;
        Bs[lk + 0][lr] = w.x;
        Bs[lk + 1][lr] = w.y;
        Bs[lk + 2][lr] = w.z;
        Bs[lk + 3][lr] = w.w;
        __syncthreads();

#pragma unroll
        for (int kt = 0; kt < 4; ++kt) {
            float4 a0 = *(const float4*)&As[ty * 4 + 0][kt * 4];
            float4 a1 = *(const float4*)&As[ty * 4 + 1][kt * 4];
            float4 a2 = *(const float4*)&As[ty * 4 + 2][kt * 4];
            float4 a3 = *(const float4*)&As[ty * 4 + 3][kt * 4];
            float ar[4][4] = {{a0.x, a0.y, a0.z, a0.w},
                              {a1.x, a1.y, a1.z, a1.w},
                              {a2.x, a2.y, a2.z, a2.w},
                              {a3.x, a3.y, a3.z, a3.w}};
#pragma unroll
            for (int kk = 0; kk < 4; ++kk) {
                float4 bv = *(const float4*)&Bs[kt * 4 + kk][tx * 4];
                float bb[4] = {bv.x, bv.y, bv.z, bv.w};
#pragma unroll
                for (int i = 0; i < 4; ++i)
#pragma unroll
                    for (int j = 0; j < 4; ++j)
                        acc[i][j] += ar[i][kk] * bb[j];
            }
        }
        __syncthreads();
    }

    float4 bia = *(const float4*)(bias + col0 + tx * 4);
#pragma unroll
    for (int i = 0; i < 4; ++i) {
        size_t base = (size_t)(row0 + ty * 4 + i) * DD + col0 + tx * 4;
        float4 r;
        r.x = acc[i][0] + bia.x;
        r.y = acc[i][1] + bia.y;
        r.z = acc[i][2] + bia.z;
        r.w = acc[i][3] + bia.w;
        *(float4*)(C + base) = r;
    }
}

// ---------------------------------------------------------------------------
// NN GEMM + fused epilogue:
//   acc[n,d] = sum_k adj[b,n,k] * xWr[b,k,d]
//   val = relu((acc + xW0[b,n,d]) / denom[b,n])
//   if final: out[b,n,d] = nodes[b,n,d] + val   (final residual, to d_out)
//   else:     g_x[b,n,d] = val
//   grid: (DD/64=4 col tiles, NN/64=32 row tiles, BB=8)
// ---------------------------------------------------------------------------
__global__ void gemm_nn_epi_kernel(const float* __restrict__ adj,
                                   const float* __restrict__ nodes,
                                   float* __restrict__ dout,
                                   int final_layer) {
    __shared__ float As[64][16];      // adj tile [row][k]
    __shared__ float Bs[16][64];      // xWr tile [k][col]

    int b = blockIdx.z;
    const float* A  = adj   + (size_t)b * NN * NN;
    const float* Bm = g_xWr + (size_t)b * NN * DD;

    int tid = threadIdx.x;
    int tx = tid & 15;
    int ty = tid >> 4;
    int row0 = blockIdx.y * 64;
    int col0 = blockIdx.x * 64;

    int alr = tid >> 2;        // A tile row 0..63
    int alk = (tid & 3) * 4;   // A k offset
    int bk  = tid >> 4;        // B tile k row 0..15
    int bj  = (tid & 15) * 4;  // B col offset

    float acc[4][4] = {};

    for (int k0 = 0; k0 < NN; k0 += 16) {
        float4 a = *(const float4*)(A + (size_t)(row0 + alr) * NN + k0 + alk);
        *(float4*)&As[alr][alk] = a;
        float4 bv4 = *(const float4*)(Bm + (size_t)(k0 + bk) * DD + col0 + bj);
        *(float4*)&Bs[bk][bj] = bv4;
        __syncthreads();

#pragma unroll
        for (int kt = 0; kt < 4; ++kt) {
            float4 a0 = *(const float4*)&As[ty * 4 + 0][kt * 4];
            float4 a1 = *(const float4*)&As[ty * 4 + 1][kt * 4];
            float4 a2 = *(const float4*)&As[ty * 4 + 2][kt * 4];
            float4 a3 = *(const float4*)&As[ty * 4 + 3][kt * 4];
            float ar[4][4] = {{a0.x, a0.y, a0.z, a0.w},
                              {a1.x, a1.y, a1.z, a1.w},
                              {a2.x, a2.y, a2.z, a2.w},
                              {a3.x, a3.y, a3.z, a3.w}};
#pragma unroll
            for (int kk = 0; kk < 4; ++kk) {
                float4 bv = *(const float4*)&Bs[kt * 4 + kk][tx * 4];
                float bb[4] = {bv.x, bv.y, bv.z, bv.w};
#pragma unroll
                for (int i = 0; i < 4; ++i)
#pragma unroll
                    for (int j = 0; j < 4; ++j)
                        acc[i][j] += ar[i][kk] * bb[j];
            }
        }
        __syncthreads();
    }

    // Epilogue
#pragma unroll
    for (int i = 0; i < 4; ++i) {
        int row = row0 + ty * 4 + i;
        float inv = 1.0f / g_denom[b * NN + row];
        size_t base = ((size_t)b * NN + row) * DD + col0 + tx * 4;
        float4 ad = *(const float4*)(g_xW0 + base);
        float4 r;
        r.x = fmaxf((acc[i][0] + ad.x) * inv, 0.0f);
        r.y = fmaxf((acc[i][1] + ad.y) * inv, 0.0f);
        r.z = fmaxf((acc[i][2] + ad.z) * inv, 0.0f);
        r.w = fmaxf((acc[i][3] + ad.w) * inv, 0.0f);
        if (final_layer) {
            float4 nv = *(const float4*)(nodes + base);
            r.x += nv.x; r.y += nv.y; r.z += nv.z; r.w += nv.w;
            *(float4*)(dout + base) = r;
        } else {
            *(float4*)(g_x + base) = r;
        }
    }
}

// ---------------------------------------------------------------------------
// Launch
//   Inputs (metadata order): nodes[B,N,D], adj[B,N,N], W0_w[L,D,D], W0_b[L,D],
//                            Wr_w[L,D,D], Wr_b[L,D]
//   Output: float32 [B,N,D]
// ---------------------------------------------------------------------------
extern "C" void kernel_launch(void* const* d_in, const int* in_sizes, int n_in,
                              void* d_out, int out_size) {
    const float* nodes = (const float*)d_in[0];
    const float* adj   = (const float*)d_in[1];
    const float* W0w   = (const float*)d_in[2];
    const float* W0b   = (const float*)d_in[3];
    const float* Wrw   = (const float*)d_in[4];
    const float* Wrb   = (const float*)d_in[5];
    float* out = (float*)d_out;

    // denom once
    denom_kernel<<<MROWS / 8, 256>>>(adj);

    dim3 grid_nt(DD / 64, MROWS / 64);         // (4, 256)
    dim3 grid_nn(DD / 64, NN / 64, BB);        // (4, 32, 8)

    for (int l = 0; l < LL; ++l) {
        const float* wr = Wrw + (size_t)l * DD * DD;
        const float* br = Wrb + (size_t)l * DD;
        const float* w0 = W0w + (size_t)l * DD * DD;
        const float* b0 = W0b + (size_t)l * DD;
        int src = (l == 0) ? 0 : 1;
        gemm_nt_kernel<<<grid_nt, 256>>>(nodes, wr, br, src, 0);   // -> g_xWr
        gemm_nt_kernel<<<grid_nt, 256>>>(nodes, w0, b0, src, 1);   // -> g_xW0
        gemm_nn_epi_kernel<<<grid_nn, 256>>>(adj, nodes, out, (l == LL - 1) ? 1 : 0);
    }
}

// round 4
// speedup vs baseline: 2.7447x; 2.7447x over previous
#include <cuda_runtime.h>
#include <cuda_bf16.h>
#include <cstdint>

// Problem constants
#define BB 8
#define NN 2048
#define DD 256
#define LL 2
#define MROWS (BB * NN)   // 16384

#define KC 64             // K per pipeline chunk
#define NCHUNK (NN / KC)  // 32
#define NSTAGES 3

// NN-kernel smem geometry (padded, no swizzle)
#define PADK 72                      // 64 + 8 bf16 pad
#define ROWB (PADK * 2)              // 144 bytes per row
#define ASTAGE (128 * ROWB)          // 18432 B
#define STAGE_BYTES (2 * ASTAGE)     // 36864 B (A + B)
#define NN_SMEM (NSTAGES * STAGE_BYTES)  // 110592 B

// ---------------------------------------------------------------------------
// Scratch (static __device__ arrays — no allocation allowed)
// ---------------------------------------------------------------------------
__device__ __nv_bfloat16 g_adj_bf[(size_t)BB * NN * NN];   // adj in bf16
__device__ __nv_bfloat16 g_xWrT[(size_t)BB * DD * NN];     // (x@Wr^T+br)^T, [b][d][n]
__device__ float g_xW0[(size_t)BB * NN * DD];              // x @ W0^T + b0
__device__ float g_x[(size_t)BB * NN * DD];                // layer activations
__device__ float g_denom[BB * NN];                         // row-sum(adj) + 1

// ---------------------------------------------------------------------------
// PTX helpers (plain-sm_103-safe: cp.async / ldmatrix / mma.sync only)
// ---------------------------------------------------------------------------
__device__ __forceinline__ uint32_t smem_u32(const void* p) {
    uint32_t a;
    asm("{ .reg .u64 t; cvta.to.shared.u64 t, %1; cvt.u32.u64 %0, t; }" : "=r"(a) : "l"(p));
    return a;
}
__device__ __forceinline__ void cp_async16(uint32_t saddr, const void* g) {
    asm volatile("cp.async.cg.shared.global [%0], [%1], 16;" :: "r"(saddr), "l"(g) : "memory");
}
__device__ __forceinline__ void cp_commit() {
    asm volatile("cp.async.commit_group;" ::: "memory");
}
template <int N>
__device__ __forceinline__ void cp_wait() {
    asm volatile("cp.async.wait_group %0;" :: "n"(N) : "memory");
}
__device__ __forceinline__ void ldsm_x4(uint32_t (&r)[4], uint32_t addr) {
    asm volatile("ldmatrix.sync.aligned.m8n8.x4.shared.b16 {%0,%1,%2,%3}, [%4];"
                 : "=r"(r[0]), "=r"(r[1]), "=r"(r[2]), "=r"(r[3]) : "r"(addr));
}
__device__ __forceinline__ void mma_bf16(float (&c)[4], const uint32_t (&a)[4],
                                         uint32_t b0, uint32_t b1) {
    asm volatile(
        "mma.sync.aligned.m16n8k16.row.col.f32.bf16.bf16.f32 "
        "{%0,%1,%2,%3}, {%4,%5,%6,%7}, {%8,%9}, {%0,%1,%2,%3};"
        : "+f"(c[0]), "+f"(c[1]), "+f"(c[2]), "+f"(c[3])
        : "r"(a[0]), "r"(a[1]), "r"(a[2]), "r"(a[3]), "r"(b0), "r"(b1));
}

// ---------------------------------------------------------------------------
// Kernel 1: adj fp32 -> bf16 conversion fused with denom row-sum
// ---------------------------------------------------------------------------
__global__ void convert_denom_kernel(const float* __restrict__ adj) {
    int row = blockIdx.x;
    int tid = threadIdx.x;
    const float4* src = (const float4*)(adj + (size_t)row * NN);
    __nv_bfloat16* dst = g_adj_bf + (size_t)row * NN;

    float4 v0 = src[tid * 2 + 0];
    float4 v1 = src[tid * 2 + 1];
    float s = v0.x + v0.y + v0.z + v0.w + v1.x + v1.y + v1.z + v1.w;
    __nv_bfloat16 tmp[8];
    tmp[0] = __float2bfloat16(v0.x); tmp[1] = __float2bfloat16(v0.y);
    tmp[2] = __float2bfloat16(v0.z); tmp[3] = __float2bfloat16(v0.w);
    tmp[4] = __float2bfloat16(v1.x); tmp[5] = __float2bfloat16(v1.y);
    tmp[6] = __float2bfloat16(v1.z); tmp[7] = __float2bfloat16(v1.w);
    *(uint4*)(dst + tid * 8) = *(const uint4*)tmp;

    __shared__ float red[8];
#pragma unroll
    for (int o = 16; o; o >>= 1) s += __shfl_xor_sync(0xffffffffu, s, o);
    if ((tid & 31) == 0) red[tid >> 5] = s;
    __syncthreads();
    if (tid < 8) {
        float t = red[tid];
#pragma unroll
        for (int o = 4; o; o >>= 1) t += __shfl_xor_sync(0xffu, t, o);
        if (tid == 0) g_denom[row] = t + 1.0f;
    }
}

// ---------------------------------------------------------------------------
// NT GEMM (W0 branch): C[n,m] = sum_d X[n,d]*W[m,d] + bias[m] -> g_xW0 (fp32)
// ---------------------------------------------------------------------------
__global__ void gemm_nt_w0_kernel(const float* __restrict__ nodes,
                                  const float* __restrict__ W,
                                  const float* __restrict__ bias,
                                  int src_is_gx) {
    __shared__ float As[64][16];
    __shared__ float Bs[16][68];

    const float* X = src_is_gx ? g_x : nodes;
    float* C = g_xW0;

    int tid = threadIdx.x;
    int tx = tid & 15, ty = tid >> 4;
    int row0 = blockIdx.y * 64, col0 = blockIdx.x * 64;
    int lr = tid >> 2, lk = (tid & 3) * 4;

    float acc[4][4] = {};

    for (int k0 = 0; k0 < DD; k0 += 16) {
        float4 a = *(const float4*)(X + (size_t)(row0 + lr) * DD + k0 + lk);
        float4 w = *(const float4*)(W + (size_t)(col0 + lr) * DD + k0 + lk);
        *(float4*)&As[lr][lk] = a;
        Bs[lk + 0][lr] = w.x; Bs[lk + 1][lr] = w.y;
        Bs[lk + 2][lr] = w.z; Bs[lk + 3][lr] = w.w;
        __syncthreads();
#pragma unroll
        for (int kt = 0; kt < 4; ++kt) {
            float4 a0 = *(const float4*)&As[ty * 4 + 0][kt * 4];
            float4 a1 = *(const float4*)&As[ty * 4 + 1][kt * 4];
            float4 a2 = *(const float4*)&As[ty * 4 + 2][kt * 4];
            float4 a3 = *(const float4*)&As[ty * 4 + 3][kt * 4];
            float ar[4][4] = {{a0.x, a0.y, a0.z, a0.w}, {a1.x, a1.y, a1.z, a1.w},
                              {a2.x, a2.y, a2.z, a2.w}, {a3.x, a3.y, a3.z, a3.w}};
#pragma unroll
            for (int kk = 0; kk < 4; ++kk) {
                float4 bv = *(const float4*)&Bs[kt * 4 + kk][tx * 4];
                float bb[4] = {bv.x, bv.y, bv.z, bv.w};
#pragma unroll
                for (int i = 0; i < 4; ++i)
#pragma unroll
                    for (int j = 0; j < 4; ++j)
                        acc[i][j] += ar[i][kk] * bb[j];
            }
        }
        __syncthreads();
    }

    float4 bia = *(const float4*)(bias + col0 + tx * 4);
#pragma unroll
    for (int i = 0; i < 4; ++i) {
        size_t base = (size_t)(row0 + ty * 4 + i) * DD + col0 + tx * 4;
        float4 r;
        r.x = acc[i][0] + bia.x; r.y = acc[i][1] + bia.y;
        r.z = acc[i][2] + bia.z; r.w = acc[i][3] + bia.w;
        *(float4*)(C + base) = r;
    }
}

// ---------------------------------------------------------------------------
// NT GEMM (Wr branch): xWr[n,m] -> TRANSPOSED bf16 g_xWrT[b][m][n_local]
// ---------------------------------------------------------------------------
__global__ void gemm_nt_wr_kernel(const float* __restrict__ nodes,
                                  const float* __restrict__ W,
                                  const float* __restrict__ bias,
                                  int src_is_gx) {
    __shared__ float As[64][16];
    __shared__ float Bs[16][68];
    __shared__ alignas(16) __nv_bfloat16 Ts[64][72];

    const float* X = src_is_gx ? g_x : nodes;

    int tid = threadIdx.x;
    int tx = tid & 15, ty = tid >> 4;
    int row0 = blockIdx.y * 64, col0 = blockIdx.x * 64;
    int lr = tid >> 2, lk = (tid & 3) * 4;

    float acc[4][4] = {};

    for (int k0 = 0; k0 < DD; k0 += 16) {
        float4 a = *(const float4*)(X + (size_t)(row0 + lr) * DD + k0 + lk);
        float4 w = *(const float4*)(W + (size_t)(col0 + lr) * DD + k0 + lk);
        *(float4*)&As[lr][lk] = a;
        Bs[lk + 0][lr] = w.x; Bs[lk + 1][lr] = w.y;
        Bs[lk + 2][lr] = w.z; Bs[lk + 3][lr] = w.w;
        __syncthreads();
#pragma unroll
        for (int kt = 0; kt < 4; ++kt) {
            float4 a0 = *(const float4*)&As[ty * 4 + 0][kt * 4];
            float4 a1 = *(const float4*)&As[ty * 4 + 1][kt * 4];
            float4 a2 = *(const float4*)&As[ty * 4 + 2][kt * 4];
            float4 a3 = *(const float4*)&As[ty * 4 + 3][kt * 4];
            float ar[4][4] = {{a0.x, a0.y, a0.z, a0.w}, {a1.x, a1.y, a1.z, a1.w},
                              {a2.x, a2.y, a2.z, a2.w}, {a3.x, a3.y, a3.z, a3.w}};
#pragma unroll
            for (int kk = 0; kk < 4; ++kk) {
                float4 bv = *(const float4*)&Bs[kt * 4 + kk][tx * 4];
                float bb[4] = {bv.x, bv.y, bv.z, bv.w};
#pragma unroll
                for (int i = 0; i < 4; ++i)
#pragma unroll
                    for (int j = 0; j < 4; ++j)
                        acc[i][j] += ar[i][kk] * bb[j];
            }
        }
        __syncthreads();
    }

    float4 bia = *(const float4*)(bias + col0 + tx * 4);
    float bb4[4] = {bia.x, bia.y, bia.z, bia.w};
#pragma unroll
    for (int i = 0; i < 4; ++i)
#pragma unroll
        for (int j = 0; j < 4; ++j)
            Ts[tx * 4 + j][ty * 4 + i] = __float2bfloat16(acc[i][j] + bb4[j]);
    __syncthreads();

    int m = tid >> 2;
    int nc = (tid & 3) * 16;
    int b = row0 >> 11;
    int nloc = row0 & 2047;
    __nv_bfloat16* dst = g_xWrT + (size_t)b * DD * NN + (size_t)(col0 + m) * NN + nloc + nc;
    *(uint4*)(dst + 0) = *(const uint4*)&Ts[m][nc + 0];
    *(uint4*)(dst + 8) = *(const uint4*)&Ts[m][nc + 8];
}

// ---------------------------------------------------------------------------
// NN GEMM on mma.sync (bf16 HMMA) + fused epilogue
//   CTA tile 128x128, 8 warps (4M x 2N), warp tile 32x64
//   A = adj bf16 [m][k], B = xWrT bf16 [n][k] (both K-major, plain ldmatrix)
//   grid = (DD/128=2, NN/128=16, BB=8) = 256 CTAs
// ---------------------------------------------------------------------------
__global__ void __launch_bounds__(256, 2)
nn_mma_kernel(const float* __restrict__ nodes, float* __restrict__ dout,
              int final_layer) {
    extern __shared__ char smem[];
    uint32_t sb = smem_u32(smem);

    int tid = threadIdx.x;
    int lane = tid & 31, wid = tid >> 5;
    int warp_m = wid & 3, warp_n = wid >> 2;
    int b = blockIdx.z;
    int row0 = blockIdx.y * 128;
    int col0 = blockIdx.x * 128;

    const __nv_bfloat16* Ag = g_adj_bf + (size_t)b * NN * NN + (size_t)row0 * NN;
    const __nv_bfloat16* Bg = g_xWrT + (size_t)b * DD * NN + (size_t)col0 * NN;

    float acc[2][8][4];
#pragma unroll
    for (int i = 0; i < 2; ++i)
#pragma unroll
        for (int j = 0; j < 8; ++j)
#pragma unroll
            for (int q = 0; q < 4; ++q) acc[i][j][q] = 0.f;

    // ldmatrix per-thread base addrs (stage 0)
    uint32_t a_base = sb + (uint32_t)((warp_m * 32 + (lane & 15)) * ROWB + ((lane >> 4) * 8) * 2);
    uint32_t b_base = sb + ASTAGE +
                      (uint32_t)((warp_n * 64 + (lane & 15)) * ROWB + ((lane >> 4) * 8) * 2);

    // FIXED loader: 128 rows x 8 chunks x 16B per operand (full 64-K chunk)
    auto load_stage = [&](int c, int s) {
        uint32_t as = sb + s * STAGE_BYTES;
        uint32_t bs = as + ASTAGE;
        int k0 = c * KC;
#pragma unroll
        for (int i = 0; i < 4; ++i) {
            int idx = i * 256 + tid;
            int r = idx >> 3, ch = idx & 7;
            cp_async16(as + r * ROWB + ch * 16, Ag + (size_t)r * NN + k0 + ch * 8);
        }
#pragma unroll
        for (int i = 0; i < 4; ++i) {
            int idx = i * 256 + tid;
            int r = idx >> 3, ch = idx & 7;
            cp_async16(bs + r * ROWB + ch * 16, Bg + (size_t)r * NN + k0 + ch * 8);
        }
        cp_commit();
    };

    auto compute_stage = [&](int s) {
        uint32_t as = a_base + s * STAGE_BYTES;
        uint32_t bs = b_base + s * STAGE_BYTES;
#pragma unroll
        for (int ks = 0; ks < 4; ++ks) {
            uint32_t af[2][4];
            ldsm_x4(af[0], as + 0 * 16 * ROWB + ks * 32);
            ldsm_x4(af[1], as + 1 * 16 * ROWB + ks * 32);
            uint32_t bf[4][4];
#pragma unroll
            for (int n2 = 0; n2 < 4; ++n2)
                ldsm_x4(bf[n2], bs + n2 * 16 * ROWB + ks * 32);
#pragma unroll
            for (int mf = 0; mf < 2; ++mf)
#pragma unroll
                for (int nf = 0; nf < 8; ++nf)
                    mma_bf16(acc[mf][nf], af[mf], bf[nf >> 1][nf & 1],
                             bf[nf >> 1][(nf & 1) + 2]);
        }
    };

    load_stage(0, 0);
    load_stage(1, 1);

    for (int c = 0; c < NCHUNK; ++c) {
        if (c + 1 < NCHUNK) cp_wait<1>(); else cp_wait<0>();
        __syncthreads();
        if (c + 2 < NCHUNK) load_stage(c + 2, (c + 2) % NSTAGES);
        compute_stage(c % NSTAGES);
    }

    // --- fused epilogue straight from accumulators ---
    int g = lane >> 2, tg = lane & 3;
#pragma unroll
    for (int mf = 0; mf < 2; ++mf) {
#pragma unroll
        for (int half = 0; half < 2; ++half) {
            int row = row0 + warp_m * 32 + mf * 16 + half * 8 + g;
            size_t grow = (size_t)b * NN + row;
            float inv = 1.0f / g_denom[grow];
            const float* w0r = g_xW0 + grow * DD;
            const float* ndr = nodes + grow * DD;
            float* xr = g_x + grow * DD;
            float* orr = dout + grow * DD;
#pragma unroll
            for (int nf = 0; nf < 8; ++nf) {
                int col = col0 + warp_n * 64 + nf * 8 + tg * 2;
                float2 w0 = *(const float2*)(w0r + col);
                float vx = fmaxf((acc[mf][nf][half * 2 + 0] + w0.x) * inv, 0.f);
                float vy = fmaxf((acc[mf][nf][half * 2 + 1] + w0.y) * inv, 0.f);
                if (final_layer) {
                    float2 nd = *(const float2*)(ndr + col);
                    vx += nd.x; vy += nd.y;
                    *(float2*)(orr + col) = make_float2(vx, vy);
                } else {
                    *(float2*)(xr + col) = make_float2(vx, vy);
                }
            }
        }
    }
}

// ---------------------------------------------------------------------------
// Launch
// ---------------------------------------------------------------------------
extern "C" void kernel_launch(void* const* d_in, const int* in_sizes, int n_in,
                              void* d_out, int out_size) {
    const float* nodes = (const float*)d_in[0];
    const float* adj   = (const float*)d_in[1];
    const float* W0w   = (const float*)d_in[2];
    const float* W0b   = (const float*)d_in[3];
    const float* Wrw   = (const float*)d_in[4];
    const float* Wrb   = (const float*)d_in[5];
    float* out = (float*)d_out;

    cudaFuncSetAttribute(nn_mma_kernel, cudaFuncAttributeMaxDynamicSharedMemorySize,
                         NN_SMEM);

    convert_denom_kernel<<<MROWS, 256>>>(adj);

    dim3 grid_nt(DD / 64, MROWS / 64);     // (4, 256)
    dim3 grid_nn(DD / 128, NN / 128, BB);  // (2, 16, 8)

    for (int l = 0; l < LL; ++l) {
        const float* wr = Wrw + (size_t)l * DD * DD;
        const float* br = Wrb + (size_t)l * DD;
        const float* w0 = W0w + (size_t)l * DD * DD;
        const float* b0 = W0b + (size_t)l * DD;
        int src = (l == 0) ? 0 : 1;
        gemm_nt_wr_kernel<<<grid_nt, 256>>>(nodes, wr, br, src);   // -> g_xWrT (bf16)
        gemm_nt_w0_kernel<<<grid_nt, 256>>>(nodes, w0, b0, src);   // -> g_xW0 (fp32)
        nn_mma_kernel<<<grid_nn, 256, NN_SMEM>>>(nodes, out, (l == LL - 1) ? 1 : 0);
    }
}

// round 6
// speedup vs baseline: 5.0170x; 1.8279x over previous
#include <cuda_runtime.h>
#include <cuda_bf16.h>
#include <cstdint>

// Problem constants
#define BB 8
#define NN 2048
#define DD 256
#define LL 2
#define MROWS (BB * NN)   // 16384

#define KC 64             // K per pipeline chunk
#define NSTAGES 3

// smem geometry (padded, no swizzle) — shared by both MMA kernels
#define PADK 72                      // 64 + 8 bf16 pad
#define ROWB (PADK * 2)              // 144 bytes per row
#define ASTAGE (128 * ROWB)          // 18432 B
#define STAGE_BYTES (2 * ASTAGE)     // 36864 B (A + B)
#define MMA_SMEM (NSTAGES * STAGE_BYTES)  // 110592 B

// ---------------------------------------------------------------------------
// Scratch (static __device__ arrays — no allocation allowed)
// ---------------------------------------------------------------------------
__device__ __nv_bfloat16 g_adj_bf[(size_t)BB * NN * NN];    // adj bf16
__device__ __nv_bfloat16 g_nodes_bf[(size_t)MROWS * DD];    // nodes bf16
__device__ __nv_bfloat16 g_xbf[(size_t)MROWS * DD];         // activations bf16
__device__ __nv_bfloat16 g_xWrT[(size_t)BB * DD * NN];      // (x@Wr^T+br)^T bf16
__device__ __nv_bfloat16 g_W0bf[(size_t)LL * DD * DD];      // W0_w bf16
__device__ __nv_bfloat16 g_Wrbf[(size_t)LL * DD * DD];      // Wr_w bf16
__device__ float g_xW0[(size_t)MROWS * DD];                 // x @ W0^T + b0 (fp32)
__device__ float g_denom[MROWS];                            // row-sum(adj) + 1

// ---------------------------------------------------------------------------
// PTX helpers (plain-sm_103-safe)
// ---------------------------------------------------------------------------
__device__ __forceinline__ uint32_t smem_u32(const void* p) {
    uint32_t a;
    asm("{ .reg .u64 t; cvta.to.shared.u64 t, %1; cvt.u32.u64 %0, t; }" : "=r"(a) : "l"(p));
    return a;
}
__device__ __forceinline__ void cp_async16(uint32_t saddr, const void* g) {
    asm volatile("cp.async.cg.shared.global [%0], [%1], 16;" :: "r"(saddr), "l"(g) : "memory");
}
__device__ __forceinline__ void cp_commit() {
    asm volatile("cp.async.commit_group;" ::: "memory");
}
template <int N>
__device__ __forceinline__ void cp_wait() {
    asm volatile("cp.async.wait_group %0;" :: "n"(N) : "memory");
}
__device__ __forceinline__ void ldsm_x4(uint32_t (&r)[4], uint32_t addr) {
    asm volatile("ldmatrix.sync.aligned.m8n8.x4.shared.b16 {%0,%1,%2,%3}, [%4];"
                 : "=r"(r[0]), "=r"(r[1]), "=r"(r[2]), "=r"(r[3]) : "r"(addr));
}
__device__ __forceinline__ void mma_bf16(float (&c)[4], const uint32_t (&a)[4],
                                         uint32_t b0, uint32_t b1) {
    asm volatile(
        "mma.sync.aligned.m16n8k16.row.col.f32.bf16.bf16.f32 "
        "{%0,%1,%2,%3}, {%4,%5,%6,%7}, {%8,%9}, {%0,%1,%2,%3};"
        : "+f"(c[0]), "+f"(c[1]), "+f"(c[2]), "+f"(c[3])
        : "r"(a[0]), "r"(a[1]), "r"(a[2]), "r"(a[3]), "r"(b0), "r"(b1));
}
__device__ __forceinline__ uint32_t pack_bf16x2(float x, float y) {
    __nv_bfloat162 v = __floats2bfloat162_rn(x, y);
    return *(uint32_t*)&v;
}

// ---------------------------------------------------------------------------
// adj fp32 -> bf16 fused with denom row-sum (one block per adj row)
// ---------------------------------------------------------------------------
__global__ void convert_denom_kernel(const float* __restrict__ adj) {
    int row = blockIdx.x;
    int tid = threadIdx.x;
    const float4* src = (const float4*)(adj + (size_t)row * NN);
    __nv_bfloat16* dst = g_adj_bf + (size_t)row * NN;

    float4 v0 = src[tid * 2 + 0];
    float4 v1 = src[tid * 2 + 1];
    float s = v0.x + v0.y + v0.z + v0.w + v1.x + v1.y + v1.z + v1.w;
    __nv_bfloat16 tmp[8];
    tmp[0] = __float2bfloat16(v0.x); tmp[1] = __float2bfloat16(v0.y);
    tmp[2] = __float2bfloat16(v0.z); tmp[3] = __float2bfloat16(v0.w);
    tmp[4] = __float2bfloat16(v1.x); tmp[5] = __float2bfloat16(v1.y);
    tmp[6] = __float2bfloat16(v1.z); tmp[7] = __float2bfloat16(v1.w);
    *(uint4*)(dst + tid * 8) = *(const uint4*)tmp;

    __shared__ float red[8];
#pragma unroll
    for (int o = 16; o; o >>= 1) s += __shfl_xor_sync(0xffffffffu, s, o);
    if ((tid & 31) == 0) red[tid >> 5] = s;
    __syncthreads();
    if (tid < 8) {
        float t = red[tid];
#pragma unroll
        for (int o = 4; o; o >>= 1) t += __shfl_xor_sync(0xffu, t, o);
        if (tid == 0) g_denom[row] = t + 1.0f;
    }
}

// ---------------------------------------------------------------------------
// prep: nodes + weight matrices -> bf16 (8 fp32 per thread)
// ---------------------------------------------------------------------------
#define NB_NODES ((MROWS * DD) / (256 * 8))           // 2048
#define NB_W ((LL * DD * DD) / (256 * 8))             // 64

__global__ void convert_prep_kernel(const float* __restrict__ nodes,
                                    const float* __restrict__ W0w,
                                    const float* __restrict__ Wrw) {
    int bid = blockIdx.x;
    const float* src;
    __nv_bfloat16* dst;
    size_t off;
    if (bid < NB_NODES) {
        src = nodes; dst = g_nodes_bf; off = (size_t)bid * 256 * 8;
    } else if (bid < NB_NODES + NB_W) {
        src = W0w; dst = g_W0bf; off = (size_t)(bid - NB_NODES) * 256 * 8;
    } else {
        src = Wrw; dst = g_Wrbf; off = (size_t)(bid - NB_NODES - NB_W) * 256 * 8;
    }
    size_t p = off + (size_t)threadIdx.x * 8;
    float4 v0 = *(const float4*)(src + p);
    float4 v1 = *(const float4*)(src + p + 4);
    __nv_bfloat16 tmp[8];
    tmp[0] = __float2bfloat16(v0.x); tmp[1] = __float2bfloat16(v0.y);
    tmp[2] = __float2bfloat16(v0.z); tmp[3] = __float2bfloat16(v0.w);
    tmp[4] = __float2bfloat16(v1.x); tmp[5] = __float2bfloat16(v1.y);
    tmp[6] = __float2bfloat16(v1.z); tmp[7] = __float2bfloat16(v1.w);
    *(uint4*)(dst + p) = *(const uint4*)tmp;
}

// ---------------------------------------------------------------------------
// Fused NT GEMM on mma.sync: x@W0^T+b0 (fp32) and x@Wr^T+br (bf16, transposed)
//   A source selected IN DEVICE CODE via use_x (device symbols are not valid
//   host-side pointers).
//   grid = (4, 128), block = 256 (8 warps: 4M x 2N)
// ---------------------------------------------------------------------------
__global__ void __launch_bounds__(256, 2)
xw_mma_kernel(int use_x,
              const float* __restrict__ b0,
              const float* __restrict__ br,
              int layer) {
    extern __shared__ char smem[];
    uint32_t sb = smem_u32(smem);
    __nv_bfloat16* Ts = (__nv_bfloat16*)smem;    // aliases stage mem (epilogue only)

    int tid = threadIdx.x;
    int lane = tid & 31, wid = tid >> 5;
    int warp_m = wid & 3, warp_n = wid >> 2;
    int row0 = blockIdx.y * 128;
    int is_wr = (blockIdx.x >= 2);
    int colt = blockIdx.x & 1;
    int col0w = colt * 128;

    const __nv_bfloat16* Abase = use_x ? g_xbf : g_nodes_bf;   // FIXED: device-side select
    const __nv_bfloat16* Ag = Abase + (size_t)row0 * DD;
    const __nv_bfloat16* Bg = (is_wr ? g_Wrbf : g_W0bf) + (size_t)layer * DD * DD
                              + (size_t)col0w * DD;

    float acc[2][8][4];
#pragma unroll
    for (int i = 0; i < 2; ++i)
#pragma unroll
        for (int j = 0; j < 8; ++j)
#pragma unroll
            for (int q = 0; q < 4; ++q) acc[i][j][q] = 0.f;

    uint32_t a_base = sb + (uint32_t)((warp_m * 32 + (lane & 15)) * ROWB + ((lane >> 4) * 8) * 2);
    uint32_t b_base = sb + ASTAGE +
                      (uint32_t)((warp_n * 64 + (lane & 15)) * ROWB + ((lane >> 4) * 8) * 2);

    auto load_stage = [&](int c, int s) {
        uint32_t as = sb + s * STAGE_BYTES;
        uint32_t bs = as + ASTAGE;
        int k0 = c * KC;
#pragma unroll
        for (int i = 0; i < 4; ++i) {
            int idx = i * 256 + tid;
            int r = idx >> 3, ch = idx & 7;
            cp_async16(as + r * ROWB + ch * 16, Ag + (size_t)r * DD + k0 + ch * 8);
        }
#pragma unroll
        for (int i = 0; i < 4; ++i) {
            int idx = i * 256 + tid;
            int r = idx >> 3, ch = idx & 7;
            cp_async16(bs + r * ROWB + ch * 16, Bg + (size_t)r * DD + k0 + ch * 8);
        }
        cp_commit();
    };

    auto compute_stage = [&](int s) {
        uint32_t as = a_base + s * STAGE_BYTES;
        uint32_t bs = b_base + s * STAGE_BYTES;
#pragma unroll
        for (int ks = 0; ks < 4; ++ks) {
            uint32_t af[2][4];
            ldsm_x4(af[0], as + 0 * 16 * ROWB + ks * 32);
            ldsm_x4(af[1], as + 1 * 16 * ROWB + ks * 32);
            uint32_t bf[4][4];
#pragma unroll
            for (int n2 = 0; n2 < 4; ++n2)
                ldsm_x4(bf[n2], bs + n2 * 16 * ROWB + ks * 32);
#pragma unroll
            for (int mf = 0; mf < 2; ++mf)
#pragma unroll
                for (int nf = 0; nf < 8; ++nf)
                    mma_bf16(acc[mf][nf], af[mf], bf[nf >> 1][nf & 1],
                             bf[nf >> 1][(nf & 1) + 2]);
        }
    };

    load_stage(0, 0);
    load_stage(1, 1);
    for (int c = 0; c < 4; ++c) {            // K = 256 -> 4 chunks
        if (c + 1 < 4) cp_wait<1>(); else cp_wait<0>();
        __syncthreads();
        if (c + 2 < 4) load_stage(c + 2, (c + 2) % NSTAGES);
        compute_stage(c % NSTAGES);
    }

    const float* bias = (is_wr ? br : b0);
    int g = lane >> 2, tg = lane & 3;

    if (!is_wr) {
        // W0 branch: fp32, natural layout, straight from fragments
#pragma unroll
        for (int mf = 0; mf < 2; ++mf)
#pragma unroll
            for (int half = 0; half < 2; ++half) {
                int row = row0 + warp_m * 32 + mf * 16 + half * 8 + g;
#pragma unroll
                for (int nf = 0; nf < 8; ++nf) {
                    int col = col0w + warp_n * 64 + nf * 8 + tg * 2;
                    float2 bi = *(const float2*)(bias + col);
                    float2 r;
                    r.x = acc[mf][nf][half * 2 + 0] + bi.x;
                    r.y = acc[mf][nf][half * 2 + 1] + bi.y;
                    *(float2*)(g_xW0 + (size_t)row * DD + col) = r;
                }
            }
    } else {
        // Wr branch: bf16, staged transpose through smem, then coalesced out
        __syncthreads();   // stage smem fully consumed; safe to alias as Ts
#pragma unroll
        for (int mf = 0; mf < 2; ++mf)
#pragma unroll
            for (int half = 0; half < 2; ++half) {
                int rl = warp_m * 32 + mf * 16 + half * 8 + g;
#pragma unroll
                for (int nf = 0; nf < 8; ++nf) {
                    int cl = warp_n * 64 + nf * 8 + tg * 2;
                    float2 bi = *(const float2*)(bias + col0w + cl);
                    Ts[(size_t)cl * 136 + rl] =
                        __float2bfloat16(acc[mf][nf][half * 2 + 0] + bi.x);
                    Ts[(size_t)(cl + 1) * 136 + rl] =
                        __float2bfloat16(acc[mf][nf][half * 2 + 1] + bi.y);
                }
            }
        __syncthreads();
        int b = row0 >> 11;
        int nloc = row0 & 2047;
        int dl = tid >> 1, seg = tid & 1;
        __nv_bfloat16* dst = g_xWrT + (size_t)b * DD * NN + (size_t)(col0w + dl) * NN
                             + nloc + seg * 64;
        const __nv_bfloat16* srcp = Ts + (size_t)dl * 136 + seg * 64;
#pragma unroll
        for (int q = 0; q < 8; ++q)
            *(uint4*)(dst + q * 8) = *(const uint4*)(srcp + q * 8);
    }
}

// ---------------------------------------------------------------------------
// NN GEMM on mma.sync + fused epilogue
//   grid = (DD/128=2, NN/128=16, BB=8) = 256 CTAs
// ---------------------------------------------------------------------------
#define NCHUNK (NN / KC)  // 32

__global__ void __launch_bounds__(256, 2)
nn_mma_kernel(const float* __restrict__ nodes, float* __restrict__ dout,
              int final_layer) {
    extern __shared__ char smem[];
    uint32_t sb = smem_u32(smem);

    int tid = threadIdx.x;
    int lane = tid & 31, wid = tid >> 5;
    int warp_m = wid & 3, warp_n = wid >> 2;
    int b = blockIdx.z;
    int row0 = blockIdx.y * 128;
    int col0 = blockIdx.x * 128;

    const __nv_bfloat16* Ag = g_adj_bf + (size_t)b * NN * NN + (size_t)row0 * NN;
    const __nv_bfloat16* Bg = g_xWrT + (size_t)b * DD * NN + (size_t)col0 * NN;

    float acc[2][8][4];
#pragma unroll
    for (int i = 0; i < 2; ++i)
#pragma unroll
        for (int j = 0; j < 8; ++j)
#pragma unroll
            for (int q = 0; q < 4; ++q) acc[i][j][q] = 0.f;

    uint32_t a_base = sb + (uint32_t)((warp_m * 32 + (lane & 15)) * ROWB + ((lane >> 4) * 8) * 2);
    uint32_t b_base = sb + ASTAGE +
                      (uint32_t)((warp_n * 64 + (lane & 15)) * ROWB + ((lane >> 4) * 8) * 2);

    auto load_stage = [&](int c, int s) {
        uint32_t as = sb + s * STAGE_BYTES;
        uint32_t bs = as + ASTAGE;
        int k0 = c * KC;
#pragma unroll
        for (int i = 0; i < 4; ++i) {
            int idx = i * 256 + tid;
            int r = idx >> 3, ch = idx & 7;
            cp_async16(as + r * ROWB + ch * 16, Ag + (size_t)r * NN + k0 + ch * 8);
        }
#pragma unroll
        for (int i = 0; i < 4; ++i) {
            int idx = i * 256 + tid;
            int r = idx >> 3, ch = idx & 7;
            cp_async16(bs + r * ROWB + ch * 16, Bg + (size_t)r * NN + k0 + ch * 8);
        }
        cp_commit();
    };

    auto compute_stage = [&](int s) {
        uint32_t as = a_base + s * STAGE_BYTES;
        uint32_t bs = b_base + s * STAGE_BYTES;
#pragma unroll
        for (int ks = 0; ks < 4; ++ks) {
            uint32_t af[2][4];
            ldsm_x4(af[0], as + 0 * 16 * ROWB + ks * 32);
            ldsm_x4(af[1], as + 1 * 16 * ROWB + ks * 32);
            uint32_t bf[4][4];
#pragma unroll
            for (int n2 = 0; n2 < 4; ++n2)
                ldsm_x4(bf[n2], bs + n2 * 16 * ROWB + ks * 32);
#pragma unroll
            for (int mf = 0; mf < 2; ++mf)
#pragma unroll
                for (int nf = 0; nf < 8; ++nf)
                    mma_bf16(acc[mf][nf], af[mf], bf[nf >> 1][nf & 1],
                             bf[nf >> 1][(nf & 1) + 2]);
        }
    };

    load_stage(0, 0);
    load_stage(1, 1);

    for (int c = 0; c < NCHUNK; ++c) {
        if (c + 1 < NCHUNK) cp_wait<1>(); else cp_wait<0>();
        __syncthreads();
        if (c + 2 < NCHUNK) load_stage(c + 2, (c + 2) % NSTAGES);
        compute_stage(c % NSTAGES);
    }

    int g = lane >> 2, tg = lane & 3;
#pragma unroll
    for (int mf = 0; mf < 2; ++mf) {
#pragma unroll
        for (int half = 0; half < 2; ++half) {
            int row = row0 + warp_m * 32 + mf * 16 + half * 8 + g;
            size_t grow = (size_t)b * NN + row;
            float inv = 1.0f / g_denom[grow];
            const float* w0r = g_xW0 + grow * DD;
            const float* ndr = nodes + grow * DD;
            float* orr = dout + grow * DD;
            __nv_bfloat16* xr = g_xbf + grow * DD;
#pragma unroll
            for (int nf = 0; nf < 8; ++nf) {
                int col = col0 + warp_n * 64 + nf * 8 + tg * 2;
                float2 w0 = *(const float2*)(w0r + col);
                float vx = fmaxf((acc[mf][nf][half * 2 + 0] + w0.x) * inv, 0.f);
                float vy = fmaxf((acc[mf][nf][half * 2 + 1] + w0.y) * inv, 0.f);
                if (final_layer) {
                    float2 nd = *(const float2*)(ndr + col);
                    vx += nd.x; vy += nd.y;
                    *(float2*)(orr + col) = make_float2(vx, vy);
                } else {
                    *(uint32_t*)(xr + col) = pack_bf16x2(vx, vy);
                }
            }
        }
    }
}

// ---------------------------------------------------------------------------
// Launch
// ---------------------------------------------------------------------------
extern "C" void kernel_launch(void* const* d_in, const int* in_sizes, int n_in,
                              void* d_out, int out_size) {
    const float* nodes = (const float*)d_in[0];
    const float* adj   = (const float*)d_in[1];
    const float* W0w   = (const float*)d_in[2];
    const float* W0b   = (const float*)d_in[3];
    const float* Wrw   = (const float*)d_in[4];
    const float* Wrb   = (const float*)d_in[5];
    float* out = (float*)d_out;

    cudaFuncSetAttribute(nn_mma_kernel, cudaFuncAttributeMaxDynamicSharedMemorySize,
                         MMA_SMEM);
    cudaFuncSetAttribute(xw_mma_kernel, cudaFuncAttributeMaxDynamicSharedMemorySize,
                         MMA_SMEM);

    convert_denom_kernel<<<MROWS, 256>>>(adj);
    convert_prep_kernel<<<NB_NODES + 2 * NB_W, 256>>>(nodes, W0w, Wrw);

    dim3 grid_xw(4, MROWS / 128);          // (4, 128)
    dim3 grid_nn(DD / 128, NN / 128, BB);  // (2, 16, 8)

    for (int l = 0; l < LL; ++l) {
        xw_mma_kernel<<<grid_xw, 256, MMA_SMEM>>>((l == 0) ? 0 : 1,
                                                  W0b + (size_t)l * DD,
                                                  Wrb + (size_t)l * DD, l);
        nn_mma_kernel<<<grid_nn, 256, MMA_SMEM>>>(nodes, out, (l == LL - 1) ? 1 : 0);
    }
}